// round 15
// baseline (speedup 1.0000x reference)
#include <cuda_runtime.h>
#include <math.h>

// MPS log|Psi|^2, sm_103a — FINAL: R14 main kernel bit-exact (pair fusion +
// e1 + Kahan, packed f32x2, 16 thr/sample, 96% of fma-pipe roofline), with
// the prelude fused into ONE launch:
//   blocks [0, 508)      : build_G (arithmetic identical to R7/R11/R14)
//   blocks [508, 2556)   : ballot-based bit packing (warp packs a word via
//                          one coalesced 128B load + __ballot_sync)
// rel_err must remain exactly 4.171494e-4.

#define NSITES  256
#define BATCH   8192
#define NGROUP  127
#define SPC     56                 // samples per CTA: 147*56 = 8232 >= 8192
#define SGN64   0x8000000080000000ULL
#define NBUILD  (NGROUP * 4)       // 508 build blocks
#define NPACK   2048               // pack blocks (32 words each)

__device__ float        g_Gh[(size_t)NGROUP * 4 * 4096];
__device__ unsigned int g_bits[BATCH * 8];

typedef unsigned long long ull;

__device__ __forceinline__ ull f2x_mul(ull a, ull b) {
    ull d; asm("mul.rn.f32x2 %0, %1, %2;" : "=l"(d) : "l"(a), "l"(b)); return d;
}
__device__ __forceinline__ ull f2x_add(ull a, ull b) {
    ull d; asm("add.rn.f32x2 %0, %1, %2;" : "=l"(d) : "l"(a), "l"(b)); return d;
}
__device__ __forceinline__ ull f2x_fma(ull a, ull b, ull c) {
    ull d; asm("fma.rn.f32x2 %0, %1, %2, %3;" : "=l"(d) : "l"(a), "l"(b), "l"(c)); return d;
}
__device__ __forceinline__ ull packff(float x, float y) {
    ull d; asm("mov.b64 %0, {%1, %2};" : "=l"(d) : "f"(x), "f"(y)); return d;
}
__device__ __forceinline__ void unpackff(ull v, float& x, float& y) {
    asm("mov.b64 {%0, %1}, %2;" : "=f"(x), "=f"(y) : "l"(v));
}
__device__ __forceinline__ void prefetchL1(const void* p) {
    asm volatile("prefetch.global.L1 [%0];" :: "l"(p));
}

// -------------------- fused prelude: build_G (blocks < NBUILD) + pack bits
__global__ void prelude_kernel(const float* __restrict__ bulk,
                               const int*   __restrict__ cfg) {
    __shared__ float As[64 * 65];
    __shared__ float Bs[64 * 68];
    int blk = blockIdx.x;
    int tid = threadIdx.x;

    if (blk >= NBUILD) {
        // ---- bit packing: each warp packs 4 words (1 coalesced load + ballot)
        int pidx = blk - NBUILD;
        int wid  = tid >> 5, lane = tid & 31;
#pragma unroll
        for (int it = 0; it < 4; it++) {
            int W = pidx * 32 + wid * 4 + it;        // word id = row*8 + w
            unsigned int v = (unsigned int)cfg[W * 32 + lane];
            unsigned int word = __ballot_sync(0xFFFFFFFFu, v & 1u);
            if (lane == 0) g_bits[W] = word;
        }
        return;
    }

    // ---- build_G: arithmetic bit-identical to R7/R11/R14
    int g = blk >> 2, c = blk & 3;
    int v0 = c & 1, v1 = (c >> 1) & 1;
    const float* A = bulk + (size_t)(2 * g) * 8192 + v0 * 64;   // bulk[2g][i][v0][j]
    const float* B = bulk + (size_t)(2 * g + 1) * 8192 + v1 * 64;
    for (int n = tid; n < 4096; n += 256) {
        int i = n >> 6, j = n & 63;
        As[i * 65 + j] = A[i * 128 + j];
        Bs[i * 68 + j] = B[i * 128 + j];
    }
    __syncthreads();
    int r  = tid >> 2;
    int j0 = (tid & 3) * 16;
    float s[16], cc[16], ae[16];
#pragma unroll
    for (int q = 0; q < 16; q++) { s[q] = 0.f; cc[q] = 0.f; ae[q] = 0.f; }
#pragma unroll 8
    for (int k = 0; k < 64; k++) {
        float a = As[r * 65 + k];
#pragma unroll
        for (int q = 0; q < 16; q++) {
            float b  = Bs[k * 68 + j0 + q];
            float p  = a * b;
            float e1 = fmaf(a, b, -p);
            float y  = p - cc[q];
            float t  = s[q] + y;
            cc[q]    = (t - s[q]) - y;
            s[q]     = t;
            ae[q]   += e1;
        }
    }
    size_t base = ((size_t)(g * 4 + c) << 12) + r * 64 + j0;
#pragma unroll
    for (int q = 0; q < 16; q++)
        g_Gh[base + q] = s[q] + (ae[q] - cc[q]);    // ~correctly rounded
}

// --------------------------------------------------------------- main chain
__global__ __launch_bounds__(16 * SPC, 1)
void mps_main_kernel(const float* __restrict__ left,
                     const float* __restrict__ right,
                     float* __restrict__ out) {
    const int tid  = threadIdx.x;
    const int o    = tid & 15;                   // lane group: cols [4o,4o+4)
    const int row0 = blockIdx.x * SPC + (tid >> 4);
    const int row  = row0 < BATCH ? row0 : BATCH - 1;

    unsigned int B[8];
#pragma unroll
    for (int w = 0; w < 8; w++) B[w] = g_bits[row * 8 + w];
#define BIT(s) ((B[(s) >> 5] >> ((s) & 31)) & 1u)

    float env[4];
    {
        unsigned int b0 = BIT(0);
#pragma unroll
        for (int t = 0; t < 4; t++) env[t] = left[b0 * 64 + 4 * o + t];
    }
    int ls2 = 0;

    for (int g = 0; g < NGROUP; g++) {
        unsigned int c = BIT(2 * g + 1) | (BIT(2 * g + 2) << 1);
        const float* __restrict__ Gm = g_Gh + ((size_t)(g * 4 + c) << 12) + 4 * o;

        // early prefetch of NEXT group's head lines (no arithmetic effect)
        if (g + 1 < NGROUP) {
            unsigned int cn = BIT(2 * g + 3) | (BIT(2 * g + 4) << 1);
            const float* Gn = g_Gh + ((size_t)((g + 1) * 4 + cn) << 12) + 4 * o;
#pragma unroll
            for (int pr = 0; pr < 8; pr++)
                prefetchL1(Gn + (pr << 6));
        }

        ull s[2], nc[2], lo[2];
#pragma unroll
        for (int u = 0; u < 2; u++) { s[u] = 0ULL; nc[u] = 0ULL; lo[u] = 0ULL; }

#pragma unroll
        for (int i = 0; i < 64; i++) {               // full unroll (same order)
            float eh = __shfl_sync(0xFFFFFFFFu, env[i & 3], i >> 2, 16);
            ull ep = packff(eh, eh);
            float4 h0 = *(const float4*)(Gm + (i << 6));
            ull h2[2] = { packff(h0.x, h0.y), packff(h0.z, h0.w) };
#pragma unroll
            for (int u = 0; u < 2; u++) {
                ull p  = f2x_mul(ep, h2[u]);
                ull e1 = f2x_fma(ep, h2[u], p ^ SGN64);        // exact prod err
                lo[u]  = f2x_add(lo[u], e1);
                ull y  = f2x_add(p, nc[u]);                    // p - c
                ull t  = f2x_add(s[u], y);
                nc[u]  = f2x_add(f2x_add(s[u], t ^ SGN64), y); // -(new c)
                s[u]   = t;
            }
        }

        // fold s + nc + lo -> env; track group max (same order as R11)
        float m = 0.0f;
#pragma unroll
        for (int u = 0; u < 2; u++) {
            ull tot = f2x_add(s[u], f2x_add(nc[u], lo[u]));
            unpackff(tot, env[2 * u], env[2 * u + 1]);
            m = fmaxf(m, fmaxf(fabsf(env[2 * u]), fabsf(env[2 * u + 1])));
        }

        // exact power-of-2 rescale (16-lane max stays within the sample)
        m = fmaxf(m, __shfl_xor_sync(0xFFFFFFFFu, m, 1, 16));
        m = fmaxf(m, __shfl_xor_sync(0xFFFFFFFFu, m, 2, 16));
        m = fmaxf(m, __shfl_xor_sync(0xFFFFFFFFu, m, 4, 16));
        m = fmaxf(m, __shfl_xor_sync(0xFFFFFFFFu, m, 8, 16));
        int ef = (int)(__float_as_uint(m) >> 23);
        if (ef > 0) {
            ls2 += ef - 127;
            float sc = __uint_as_float((unsigned int)(254 - ef) << 23);
#pragma unroll
            for (int t = 0; t < 4; t++) env[t] *= sc;
        }
    }

    // final contraction in fp64 (cancellation-sensitive, one-shot)
    unsigned int bl = BIT(255);
    double part = 0.0;
#pragma unroll
    for (int t = 0; t < 4; t++)
        part = fma((double)env[t], (double)right[(4 * o + t) * 2 + bl], part);
    part += __shfl_xor_sync(0xFFFFFFFFu, part, 1, 16);
    part += __shfl_xor_sync(0xFFFFFFFFu, part, 2, 16);
    part += __shfl_xor_sync(0xFFFFFFFFu, part, 4, 16);
    part += __shfl_xor_sync(0xFFFFFFFFu, part, 8, 16);

    if (o == 0 && row0 < BATCH) {
        double ap = fabs(part);
        if (ap < 1e-300) ap = 1e-300;
        out[row0] = (float)(2.0 * (log(ap) + (double)ls2 * 0.6931471805599453094));
    }
#undef BIT
}

// ------------------------------------------------------------------- launch
extern "C" void kernel_launch(void* const* d_in, const int* in_sizes, int n_in,
                              void* d_out, int out_size) {
    const int*   cfg   = (const int*)d_in[0];
    const float* left  = (const float*)d_in[1];
    const float* bulk  = (const float*)d_in[2];
    const float* right = (const float*)d_in[3];
    float*       out   = (float*)d_out;

    prelude_kernel<<<NBUILD + NPACK, 256>>>(bulk, cfg);
    mps_main_kernel<<<(BATCH + SPC - 1) / SPC, 16 * SPC>>>(left, right, out);
}

// round 16
// speedup vs baseline: 1.2444x; 1.2444x over previous
#include <cuda_runtime.h>
#include <math.h>

// MPS log|Psi|^2, sm_103a — R14 numerics BIT-EXACT, instruction-dieted:
//  - sub.rn.f32x2 replaces the operand-negation XORs (4 LOP3/row removed;
//    fl(s+(-t)) == fl(s-t), FMA residual exact, negation exact -> every
//    rounded value identical, rel_err stays 4.171494e-4).
//  - e1 captured negated via a once-per-row negated broadcast (epn).
//  - prelude back to SEPARATE launches (R15 fusion regressed): ballot-based
//    pack (~3us) + unchanged build_G.

#define NSITES  256
#define BATCH   8192
#define NGROUP  127
#define SPC     56                 // samples per CTA: 147*56 = 8232 >= 8192
#define SGN64   0x8000000080000000ULL

__device__ float        g_Gh[(size_t)NGROUP * 4 * 4096];
__device__ unsigned int g_bits[BATCH * 8];

typedef unsigned long long ull;

__device__ __forceinline__ ull f2x_mul(ull a, ull b) {
    ull d; asm("mul.rn.f32x2 %0, %1, %2;" : "=l"(d) : "l"(a), "l"(b)); return d;
}
__device__ __forceinline__ ull f2x_add(ull a, ull b) {
    ull d; asm("add.rn.f32x2 %0, %1, %2;" : "=l"(d) : "l"(a), "l"(b)); return d;
}
__device__ __forceinline__ ull f2x_sub(ull a, ull b) {
    ull d; asm("sub.rn.f32x2 %0, %1, %2;" : "=l"(d) : "l"(a), "l"(b)); return d;
}
__device__ __forceinline__ ull f2x_fma(ull a, ull b, ull c) {
    ull d; asm("fma.rn.f32x2 %0, %1, %2, %3;" : "=l"(d) : "l"(a), "l"(b), "l"(c)); return d;
}
__device__ __forceinline__ ull packff(float x, float y) {
    ull d; asm("mov.b64 %0, {%1, %2};" : "=l"(d) : "f"(x), "f"(y)); return d;
}
__device__ __forceinline__ void unpackff(ull v, float& x, float& y) {
    asm("mov.b64 {%0, %1}, %2;" : "=f"(x), "=f"(y) : "l"(v));
}
__device__ __forceinline__ void prefetchL1(const void* p) {
    asm volatile("prefetch.global.L1 [%0];" :: "l"(p));
}

// ------------------------------------------- ballot-based bit packing (~3us)
__global__ void pack_bits_kernel(const int* __restrict__ cfg) {
    int wid  = (blockIdx.x * blockDim.x + threadIdx.x) >> 5;   // word id
    int lane = threadIdx.x & 31;
    unsigned int v = (unsigned int)cfg[wid * 32 + lane];
    unsigned int word = __ballot_sync(0xFFFFFFFFu, v & 1u);
    if (lane == 0) g_bits[wid] = word;
}

// ------------- pair-product table, compensated, correctly-rounded fp32 output
// (arithmetic identical to R7/R11/R14 — G bits define rel_err, do not touch)
__global__ void build_G_kernel(const float* __restrict__ bulk) {
    __shared__ float As[64 * 65];
    __shared__ float Bs[64 * 68];
    int g = blockIdx.x, c = blockIdx.y;
    int v0 = c & 1, v1 = (c >> 1) & 1;
    int tid = threadIdx.x;
    const float* A = bulk + (size_t)(2 * g) * 8192 + v0 * 64;   // bulk[2g][i][v0][j]
    const float* B = bulk + (size_t)(2 * g + 1) * 8192 + v1 * 64;
    for (int n = tid; n < 4096; n += 256) {
        int i = n >> 6, j = n & 63;
        As[i * 65 + j] = A[i * 128 + j];
        Bs[i * 68 + j] = B[i * 128 + j];
    }
    __syncthreads();
    int r  = tid >> 2;
    int j0 = (tid & 3) * 16;
    float s[16], cc[16], ae[16];
#pragma unroll
    for (int q = 0; q < 16; q++) { s[q] = 0.f; cc[q] = 0.f; ae[q] = 0.f; }
#pragma unroll 8
    for (int k = 0; k < 64; k++) {
        float a = As[r * 65 + k];
#pragma unroll
        for (int q = 0; q < 16; q++) {
            float b  = Bs[k * 68 + j0 + q];
            float p  = a * b;
            float e1 = fmaf(a, b, -p);
            float y  = p - cc[q];
            float t  = s[q] + y;
            cc[q]    = (t - s[q]) - y;
            s[q]     = t;
            ae[q]   += e1;
        }
    }
    size_t base = ((size_t)(g * 4 + c) << 12) + r * 64 + j0;
#pragma unroll
    for (int q = 0; q < 16; q++)
        g_Gh[base + q] = s[q] + (ae[q] - cc[q]);    // ~correctly rounded
}

// --------------------------------------------------------------- main chain
__global__ __launch_bounds__(16 * SPC, 1)
void mps_main_kernel(const float* __restrict__ left,
                     const float* __restrict__ right,
                     float* __restrict__ out) {
    const int tid  = threadIdx.x;
    const int o    = tid & 15;                   // lane group: cols [4o,4o+4)
    const int row0 = blockIdx.x * SPC + (tid >> 4);
    const int row  = row0 < BATCH ? row0 : BATCH - 1;

    unsigned int B[8];
#pragma unroll
    for (int w = 0; w < 8; w++) B[w] = g_bits[row * 8 + w];
#define BIT(s) ((B[(s) >> 5] >> ((s) & 31)) & 1u)

    float env[4];
    {
        unsigned int b0 = BIT(0);
#pragma unroll
        for (int t = 0; t < 4; t++) env[t] = left[b0 * 64 + 4 * o + t];
    }
    int ls2 = 0;

    for (int g = 0; g < NGROUP; g++) {
        unsigned int c = BIT(2 * g + 1) | (BIT(2 * g + 2) << 1);
        const float* __restrict__ Gm = g_Gh + ((size_t)(g * 4 + c) << 12) + 4 * o;

        // early prefetch of NEXT group's head lines (no arithmetic effect)
        if (g + 1 < NGROUP) {
            unsigned int cn = BIT(2 * g + 3) | (BIT(2 * g + 4) << 1);
            const float* Gn = g_Gh + ((size_t)((g + 1) * 4 + cn) << 12) + 4 * o;
#pragma unroll
            for (int pr = 0; pr < 8; pr++)
                prefetchL1(Gn + (pr << 6));
        }

        ull s[2], nc[2], lo[2];
#pragma unroll
        for (int u = 0; u < 2; u++) { s[u] = 0ULL; nc[u] = 0ULL; lo[u] = 0ULL; }

#pragma unroll
        for (int i = 0; i < 64; i++) {               // full unroll (same order)
            float eh  = __shfl_sync(0xFFFFFFFFu, env[i & 3], i >> 2, 16);
            float ehn = -eh;
            ull ep  = packff(eh,  eh);
            ull epn = packff(ehn, ehn);
            float4 h0 = *(const float4*)(Gm + (i << 6));
            ull h2[2] = { packff(h0.x, h0.y), packff(h0.z, h0.w) };
#pragma unroll
            for (int u = 0; u < 2; u++) {
                ull p   = f2x_mul(ep, h2[u]);
                ull e1n = f2x_fma(epn, h2[u], p);          // = -(exact prod err)
                lo[u]   = f2x_add(lo[u], e1n);             // lo = -sum(e1) exactly
                ull y   = f2x_add(p, nc[u]);               // p - c
                ull t   = f2x_add(s[u], y);
                nc[u]   = f2x_add(f2x_sub(s[u], t), y);    // -(new c), same bits
                s[u]    = t;
            }
        }

        // fold: tot = s + (nc - lo)  ==  s + (nc + sum(e1))  bit-identical
        float m = 0.0f;
#pragma unroll
        for (int u = 0; u < 2; u++) {
            ull tot = f2x_add(s[u], f2x_sub(nc[u], lo[u]));
            unpackff(tot, env[2 * u], env[2 * u + 1]);
            m = fmaxf(m, fmaxf(fabsf(env[2 * u]), fabsf(env[2 * u + 1])));
        }

        // exact power-of-2 rescale (16-lane max stays within the sample)
        m = fmaxf(m, __shfl_xor_sync(0xFFFFFFFFu, m, 1, 16));
        m = fmaxf(m, __shfl_xor_sync(0xFFFFFFFFu, m, 2, 16));
        m = fmaxf(m, __shfl_xor_sync(0xFFFFFFFFu, m, 4, 16));
        m = fmaxf(m, __shfl_xor_sync(0xFFFFFFFFu, m, 8, 16));
        int ef = (int)(__float_as_uint(m) >> 23);
        if (ef > 0) {
            ls2 += ef - 127;
            float sc = __uint_as_float((unsigned int)(254 - ef) << 23);
#pragma unroll
            for (int t = 0; t < 4; t++) env[t] *= sc;
        }
    }

    // final contraction in fp64 (cancellation-sensitive, one-shot)
    unsigned int bl = BIT(255);
    double part = 0.0;
#pragma unroll
    for (int t = 0; t < 4; t++)
        part = fma((double)env[t], (double)right[(4 * o + t) * 2 + bl], part);
    part += __shfl_xor_sync(0xFFFFFFFFu, part, 1, 16);
    part += __shfl_xor_sync(0xFFFFFFFFu, part, 2, 16);
    part += __shfl_xor_sync(0xFFFFFFFFu, part, 4, 16);
    part += __shfl_xor_sync(0xFFFFFFFFu, part, 8, 16);

    if (o == 0 && row0 < BATCH) {
        double ap = fabs(part);
        if (ap < 1e-300) ap = 1e-300;
        out[row0] = (float)(2.0 * (log(ap) + (double)ls2 * 0.6931471805599453094));
    }
#undef BIT
}

// ------------------------------------------------------------------- launch
extern "C" void kernel_launch(void* const* d_in, const int* in_sizes, int n_in,
                              void* d_out, int out_size) {
    const int*   cfg   = (const int*)d_in[0];
    const float* left  = (const float*)d_in[1];
    const float* bulk  = (const float*)d_in[2];
    const float* right = (const float*)d_in[3];
    float*       out   = (float*)d_out;

    pack_bits_kernel<<<BATCH * 8 * 32 / 256, 256>>>(cfg);
    dim3 gg(NGROUP, 4);
    build_G_kernel<<<gg, 256>>>(bulk);
    mps_main_kernel<<<(BATCH + SPC - 1) / SPC, 16 * SPC>>>(left, right, out);
}